// round 12
// baseline (speedup 1.0000x reference)
#include <cuda_runtime.h>
#include <cuda_bf16.h>
#include <cstdint>

#define N_NODES 100000
#define N_EDGES 800000
#define D_IN    256
#define D_OUT   128

#define M_TILE  96
#define TILES   1042             // ceil(100000 / 96)
#define GRID_P  148              // persistent CTAs
#define THREADS 384
#define SCAT_BLOCKS 25000        // N_EDGES*16/2/256 (2 edges per thread)

// Aggregation buffer: [N_NODES][128] = [agg_a(0:64) | agg_b(64:128)].
// BSS-zeroed at load; gemm re-zeroes each tile after consuming it.
__device__ __align__(16) float g_x[(size_t)N_NODES * 128];

// W^T tf32 image: [n=128][k=256], XOR-swizzled: word n*256 + (k ^ ((n&7)<<2))
__device__ __align__(16) uint32_t g_wt[128 * 256];

__device__ __forceinline__ uint32_t f2tf32(float f) {
    uint32_t u;
    asm("cvt.rna.tf32.f32 %0, %1;" : "=r"(u) : "f"(f));
    return u;
}

// ---------------------------------------------------------------------------
// Kernel 1: scatter-add, 2 edges x 2 types per thread (MLP=4) + W prep blocks.
// Edge reads: evict_first; atomics: evict_last (g_x stays L2-resident).
// ---------------------------------------------------------------------------
__global__ void scatter_prep_kernel(const float* __restrict__ edata_a,
                                    const int* __restrict__ recv_a,
                                    const float* __restrict__ edata_b,
                                    const int* __restrict__ recv_b,
                                    const float* __restrict__ W) {
    if (blockIdx.x >= SCAT_BLOCKS) {
        int idx = (blockIdx.x - SCAT_BLOCKS) * 256 + threadIdx.x;
        if (idx < D_IN * D_OUT) {
            int n = idx & 127;
            int k = idx >> 7;
            g_wt[n * 256 + (k ^ ((n & 7) << 2))] = f2tf32(W[k * D_OUT + n]);
        }
        return;
    }
    int idx  = blockIdx.x * 256 + threadIdx.x;     // 0 .. 6.4M-1
    int q    = idx & 15;
    int e0   = (idx >> 4) * 2;
    int e1   = e0 + 1;

    uint64_t pol_ef, pol_el;
    asm("createpolicy.fractional.L2::evict_first.b64 %0, 1.0;" : "=l"(pol_ef));
    asm("createpolicy.fractional.L2::evict_last.b64 %0, 1.0;"  : "=l"(pol_el));

    const float4* pa0 = reinterpret_cast<const float4*>(edata_a) + (size_t)e0 * 16 + q;
    const float4* pa1 = reinterpret_cast<const float4*>(edata_a) + (size_t)e1 * 16 + q;
    const float4* pb0 = reinterpret_cast<const float4*>(edata_b) + (size_t)e0 * 16 + q;
    const float4* pb1 = reinterpret_cast<const float4*>(edata_b) + (size_t)e1 * 16 + q;
    float4 va0, va1, vb0, vb1;
    asm volatile("ld.global.nc.L2::cache_hint.v4.f32 {%0,%1,%2,%3}, [%4], %5;"
                 : "=f"(va0.x), "=f"(va0.y), "=f"(va0.z), "=f"(va0.w) : "l"(pa0), "l"(pol_ef));
    asm volatile("ld.global.nc.L2::cache_hint.v4.f32 {%0,%1,%2,%3}, [%4], %5;"
                 : "=f"(va1.x), "=f"(va1.y), "=f"(va1.z), "=f"(va1.w) : "l"(pa1), "l"(pol_ef));
    asm volatile("ld.global.nc.L2::cache_hint.v4.f32 {%0,%1,%2,%3}, [%4], %5;"
                 : "=f"(vb0.x), "=f"(vb0.y), "=f"(vb0.z), "=f"(vb0.w) : "l"(pb0), "l"(pol_ef));
    asm volatile("ld.global.nc.L2::cache_hint.v4.f32 {%0,%1,%2,%3}, [%4], %5;"
                 : "=f"(vb1.x), "=f"(vb1.y), "=f"(vb1.z), "=f"(vb1.w) : "l"(pb1), "l"(pol_ef));

    int ra0 = recv_a[e0], ra1 = recv_a[e1];
    int rb0 = recv_b[e0], rb1 = recv_b[e1];
    float* da0 = g_x + (size_t)ra0 * 128 + q * 4;
    float* da1 = g_x + (size_t)ra1 * 128 + q * 4;
    float* db0 = g_x + (size_t)rb0 * 128 + 64 + q * 4;
    float* db1 = g_x + (size_t)rb1 * 128 + 64 + q * 4;

    asm volatile("red.global.L2::cache_hint.add.v4.f32 [%0], {%1,%2,%3,%4}, %5;"
                 :: "l"(da0), "f"(va0.x), "f"(va0.y), "f"(va0.z), "f"(va0.w), "l"(pol_el) : "memory");
    asm volatile("red.global.L2::cache_hint.add.v4.f32 [%0], {%1,%2,%3,%4}, %5;"
                 :: "l"(da1), "f"(va1.x), "f"(va1.y), "f"(va1.z), "f"(va1.w), "l"(pol_el) : "memory");
    asm volatile("red.global.L2::cache_hint.add.v4.f32 [%0], {%1,%2,%3,%4}, %5;"
                 :: "l"(db0), "f"(vb0.x), "f"(vb0.y), "f"(vb0.z), "f"(vb0.w), "l"(pol_el) : "memory");
    asm volatile("red.global.L2::cache_hint.add.v4.f32 [%0], {%1,%2,%3,%4}, %5;"
                 :: "l"(db1), "f"(vb1.x), "f"(vb1.y), "f"(vb1.z), "f"(vb1.w), "l"(pol_el) : "memory");
}

// ---------------------------------------------------------------------------
__device__ __forceinline__ void mma_tf32(float* d, uint32_t a0, uint32_t a1,
                                         uint32_t a2, uint32_t a3,
                                         uint32_t b0, uint32_t b1) {
    asm volatile(
        "mma.sync.aligned.m16n8k8.row.col.f32.tf32.tf32.f32 "
        "{%0,%1,%2,%3}, {%4,%5,%6,%7}, {%8,%9}, {%0,%1,%2,%3};"
        : "+f"(d[0]), "+f"(d[1]), "+f"(d[2]), "+f"(d[3])
        : "r"(a0), "r"(a1), "r"(a2), "r"(a3), "r"(b0), "r"(b1));
}

// SMEM (uint32 words): sW [0, 32768), sX [32768, 57344)  => 229376 bytes
#define SW_BASE 0
#define SX_BASE 32768
#define SMEM_WORDS 57344

// ---------------------------------------------------------------------------
// Kernel 2: persistent TF32 HMMA GEMM. 384 threads / 12 warps (3 per SMSP).
// M_TILE=96, warp grid 3(M)x4(N), warp tile 32x32. XOR-swizzled smem (no pad).
// vdata half of next tile prefetched in registers; g_x half is L2-resident.
// ---------------------------------------------------------------------------
__global__ __launch_bounds__(THREADS, 1)
void gemm_mma_kernel(const float* __restrict__ vdata,
                     const float* __restrict__ bias,
                     float* __restrict__ out) {
    extern __shared__ uint32_t smem[];
    const int tid  = threadIdx.x;
    const int wid  = tid >> 5;
    const int lane = tid & 31;
    const int grp  = lane >> 2;
    const int qp   = lane & 3;
    const int xg   = grp << 2;        // per-thread swizzle XOR

    const int m0 = (wid % 3) * 32;    // warp M band (of 96)
    const int n0 = (wid / 3) * 32;    // warp N quarter (of 128)

    // ---- Stage W^T swizzled image once (32768 words = 8192 uint4) ----
    {
        const uint4* src = reinterpret_cast<const uint4*>(g_wt);
        uint4* dst = reinterpret_cast<uint4*>(smem + SW_BASE);
        #pragma unroll
        for (int i = 0; i < 22; i++) {
            int j = i * THREADS + tid;
            if (j < 8192) dst[j] = src[j];
        }
    }

    float2 bv[4];
    #pragma unroll
    for (int j = 0; j < 4; j++)
        bv[j] = *reinterpret_cast<const float2*>(bias + n0 + j * 8 + qp * 2);

    const float4* A4 = reinterpret_cast<const float4*>(g_x);
    const float4* V4 = reinterpret_cast<const float4*>(vdata);

    int t = blockIdx.x;
    float4 vr[8];     // prefetched vdata half (8 float4/thread)

    if (t < TILES) {
        int node0 = t * M_TILE;
        #pragma unroll
        for (int i = 0; i < 8; i++) {
            int j = i * THREADS + tid;       // 0..3071
            int r = j >> 5, c4 = j & 31;
            int node = node0 + r;
            vr[i] = (node < N_NODES) ? V4[(size_t)node * 32 + c4]
                                     : make_float4(0.f, 0.f, 0.f, 0.f);
        }
    }

    while (t < TILES) {
        const int node0 = t * M_TILE;

        // ---- staging: vdata half from vr; g_x half direct (L2 hit) + re-zero ----
        #pragma unroll
        for (int i = 0; i < 8; i++) {
            int j = i * THREADS + tid;
            int r = j >> 5, c4 = j & 31;
            int rx = (r & 7) << 2;
            // vdata half (x cols 128:256), k0 = 128 + 4*c4
            {
                float4 v = vr[i];
                uint4 w = make_uint4(f2tf32(v.x), f2tf32(v.y), f2tf32(v.z), f2tf32(v.w));
                int off = SX_BASE + r * 256 + 128 + ((c4 * 4) ^ rx);
                *reinterpret_cast<uint4*>(smem + off) = w;
            }
            // g_x half (x cols 0:128), k0 = 4*c4
            {
                int node = node0 + r;
                float4 v = make_float4(0.f, 0.f, 0.f, 0.f);
                if (node < N_NODES) {
                    v = A4[(size_t)node * 32 + c4];
                    reinterpret_cast<float4*>(g_x)[(size_t)node * 32 + c4] =
                        make_float4(0.f, 0.f, 0.f, 0.f);
                }
                uint4 w = make_uint4(f2tf32(v.x), f2tf32(v.y), f2tf32(v.z), f2tf32(v.w));
                int off = SX_BASE + r * 256 + ((c4 * 4) ^ rx);
                *reinterpret_cast<uint4*>(smem + off) = w;
            }
        }
        __syncthreads();

        // ---- prefetch next tile's vdata half during compute ----
        int tn = t + GRID_P;
        if (tn < TILES) {
            int nn0 = tn * M_TILE;
            #pragma unroll
            for (int i = 0; i < 8; i++) {
                int j = i * THREADS + tid;
                int r = j >> 5, c4 = j & 31;
                int node = nn0 + r;
                vr[i] = (node < N_NODES) ? V4[(size_t)node * 32 + c4]
                                         : make_float4(0.f, 0.f, 0.f, 0.f);
            }
        }

        // ---- compute: 32 k-steps x (2 m-bands x 4 n-tiles) ----
        float acc[2][4][4];
        #pragma unroll
        for (int mb = 0; mb < 2; mb++)
            #pragma unroll
            for (int j = 0; j < 4; j++)
                #pragma unroll
                for (int c = 0; c < 4; c++) acc[mb][j][c] = 0.f;

        #pragma unroll 4
        for (int ks = 0; ks < 32; ks++) {
            int o  = ((ks * 8) ^ xg) + qp;   // swizzled col offset (k = ks*8+qp)
            int o4 = o ^ 4;                  // k + 4
            uint32_t a[2][4];
            #pragma unroll
            for (int mb = 0; mb < 2; mb++) {
                int base = SX_BASE + (m0 + mb * 16 + grp) * 256;
                a[mb][0] = smem[base + o];
                a[mb][1] = smem[base + 8 * 256 + o];
                a[mb][2] = smem[base + o4];
                a[mb][3] = smem[base + 8 * 256 + o4];
            }
            #pragma unroll
            for (int j = 0; j < 4; j++) {
                int baseB = SW_BASE + (n0 + j * 8 + grp) * 256;
                uint32_t b0 = smem[baseB + o];
                uint32_t b1 = smem[baseB + o4];
                mma_tf32(acc[0][j], a[0][0], a[0][1], a[0][2], a[0][3], b0, b1);
                mma_tf32(acc[1][j], a[1][0], a[1][1], a[1][2], a[1][3], b0, b1);
            }
        }

        // ---- epilogue ----
        #pragma unroll
        for (int mb = 0; mb < 2; mb++) {
            int row_a = node0 + m0 + mb * 16 + grp;
            int row_b = row_a + 8;
            #pragma unroll
            for (int j = 0; j < 4; j++) {
                int col = n0 + j * 8 + qp * 2;
                if (row_a < N_NODES) {
                    float2 o = make_float2(acc[mb][j][0] + bv[j].x,
                                           acc[mb][j][1] + bv[j].y);
                    *reinterpret_cast<float2*>(out + (size_t)row_a * D_OUT + col) = o;
                }
                if (row_b < N_NODES) {
                    float2 o = make_float2(acc[mb][j][2] + bv[j].x,
                                           acc[mb][j][3] + bv[j].y);
                    *reinterpret_cast<float2*>(out + (size_t)row_b * D_OUT + col) = o;
                }
            }
        }
        __syncthreads();
        t = tn;
    }
}

// ---------------------------------------------------------------------------
extern "C" void kernel_launch(void* const* d_in, const int* in_sizes, int n_in,
                              void* d_out, int out_size) {
    const float* vdata   = (const float*)d_in[0];
    const float* edata_a = (const float*)d_in[1];
    const float* edata_b = (const float*)d_in[2];
    const int*   conn_a  = (const int*)d_in[3];
    const int*   conn_b  = (const int*)d_in[4];
    const float* W       = (const float*)d_in[5];
    const float* bias    = (const float*)d_in[6];
    float*       out     = (float*)d_out;

    scatter_prep_kernel<<<SCAT_BLOCKS + 128, 256>>>(
        edata_a, conn_a + N_EDGES, edata_b, conn_b + N_EDGES, W);

    {
        size_t smem_bytes = SMEM_WORDS * sizeof(uint32_t);   // 229376
        cudaFuncSetAttribute(gemm_mma_kernel,
                             cudaFuncAttributeMaxDynamicSharedMemorySize,
                             (int)smem_bytes);
        gemm_mma_kernel<<<GRID_P, THREADS, smem_bytes>>>(vdata, bias, out);
    }
}

// round 13
// speedup vs baseline: 1.5715x; 1.5715x over previous
#include <cuda_runtime.h>
#include <cuda_bf16.h>
#include <cstdint>

#define N_NODES 100000
#define N_EDGES 800000
#define D_IN    256
#define D_OUT   128

#define M_TILE  96
#define TILES   1042             // ceil(100000 / 96)
#define GRID_P  148              // persistent CTAs
#define THREADS 384
#define SCAT_BLOCKS 25000        // N_EDGES*16/2/256 (2 edges per thread)

// Aggregation buffer: [N_NODES][128] = [agg_a(0:64) | agg_b(64:128)].
// BSS-zeroed at load; gemm re-zeroes each tile after consuming it.
__device__ __align__(16) float g_x[(size_t)N_NODES * 128];

// W^T tf32 image: [n=128][k=256], XOR-swizzled: word n*256 + (k ^ ((n&7)<<2))
__device__ __align__(16) uint32_t g_wt[128 * 256];

__device__ __forceinline__ uint32_t f2tf32(float f) {
    uint32_t u;
    asm("cvt.rna.tf32.f32 %0, %1;" : "=r"(u) : "f"(f));
    return u;
}

// ---------------------------------------------------------------------------
// Kernel 1: scatter-add, 2 edges x 2 types per thread (MLP=4) + W prep blocks.
// ---------------------------------------------------------------------------
__global__ void scatter_prep_kernel(const float* __restrict__ edata_a,
                                    const int* __restrict__ recv_a,
                                    const float* __restrict__ edata_b,
                                    const int* __restrict__ recv_b,
                                    const float* __restrict__ W) {
    if (blockIdx.x >= SCAT_BLOCKS) {
        int idx = (blockIdx.x - SCAT_BLOCKS) * 256 + threadIdx.x;
        if (idx < D_IN * D_OUT) {
            int n = idx & 127;
            int k = idx >> 7;
            g_wt[n * 256 + (k ^ ((n & 7) << 2))] = f2tf32(W[k * D_OUT + n]);
        }
        return;
    }
    int idx  = blockIdx.x * 256 + threadIdx.x;     // 0 .. 6.4M-1
    int q    = idx & 15;
    int e0   = (idx >> 4) * 2;
    int e1   = e0 + 1;

    uint64_t pol_ef, pol_el;
    asm("createpolicy.fractional.L2::evict_first.b64 %0, 1.0;" : "=l"(pol_ef));
    asm("createpolicy.fractional.L2::evict_last.b64 %0, 1.0;"  : "=l"(pol_el));

    const float4* pa0 = reinterpret_cast<const float4*>(edata_a) + (size_t)e0 * 16 + q;
    const float4* pa1 = reinterpret_cast<const float4*>(edata_a) + (size_t)e1 * 16 + q;
    const float4* pb0 = reinterpret_cast<const float4*>(edata_b) + (size_t)e0 * 16 + q;
    const float4* pb1 = reinterpret_cast<const float4*>(edata_b) + (size_t)e1 * 16 + q;
    float4 va0, va1, vb0, vb1;
    asm volatile("ld.global.nc.L2::cache_hint.v4.f32 {%0,%1,%2,%3}, [%4], %5;"
                 : "=f"(va0.x), "=f"(va0.y), "=f"(va0.z), "=f"(va0.w) : "l"(pa0), "l"(pol_ef));
    asm volatile("ld.global.nc.L2::cache_hint.v4.f32 {%0,%1,%2,%3}, [%4], %5;"
                 : "=f"(va1.x), "=f"(va1.y), "=f"(va1.z), "=f"(va1.w) : "l"(pa1), "l"(pol_ef));
    asm volatile("ld.global.nc.L2::cache_hint.v4.f32 {%0,%1,%2,%3}, [%4], %5;"
                 : "=f"(vb0.x), "=f"(vb0.y), "=f"(vb0.z), "=f"(vb0.w) : "l"(pb0), "l"(pol_ef));
    asm volatile("ld.global.nc.L2::cache_hint.v4.f32 {%0,%1,%2,%3}, [%4], %5;"
                 : "=f"(vb1.x), "=f"(vb1.y), "=f"(vb1.z), "=f"(vb1.w) : "l"(pb1), "l"(pol_ef));

    int ra0 = recv_a[e0], ra1 = recv_a[e1];
    int rb0 = recv_b[e0], rb1 = recv_b[e1];
    float* da0 = g_x + (size_t)ra0 * 128 + q * 4;
    float* da1 = g_x + (size_t)ra1 * 128 + q * 4;
    float* db0 = g_x + (size_t)rb0 * 128 + 64 + q * 4;
    float* db1 = g_x + (size_t)rb1 * 128 + 64 + q * 4;

    asm volatile("red.global.L2::cache_hint.add.v4.f32 [%0], {%1,%2,%3,%4}, %5;"
                 :: "l"(da0), "f"(va0.x), "f"(va0.y), "f"(va0.z), "f"(va0.w), "l"(pol_el) : "memory");
    asm volatile("red.global.L2::cache_hint.add.v4.f32 [%0], {%1,%2,%3,%4}, %5;"
                 :: "l"(da1), "f"(va1.x), "f"(va1.y), "f"(va1.z), "f"(va1.w), "l"(pol_el) : "memory");
    asm volatile("red.global.L2::cache_hint.add.v4.f32 [%0], {%1,%2,%3,%4}, %5;"
                 :: "l"(db0), "f"(vb0.x), "f"(vb0.y), "f"(vb0.z), "f"(vb0.w), "l"(pol_el) : "memory");
    asm volatile("red.global.L2::cache_hint.add.v4.f32 [%0], {%1,%2,%3,%4}, %5;"
                 :: "l"(db1), "f"(vb1.x), "f"(vb1.y), "f"(vb1.z), "f"(vb1.w), "l"(pol_el) : "memory");
}

// ---------------------------------------------------------------------------
__device__ __forceinline__ void mma_tf32(float* d, uint32_t a0, uint32_t a1,
                                         uint32_t a2, uint32_t a3,
                                         uint32_t b0, uint32_t b1) {
    asm volatile(
        "mma.sync.aligned.m16n8k8.row.col.f32.tf32.tf32.f32 "
        "{%0,%1,%2,%3}, {%4,%5,%6,%7}, {%8,%9}, {%0,%1,%2,%3};"
        : "+f"(d[0]), "+f"(d[1]), "+f"(d[2]), "+f"(d[3])
        : "r"(a0), "r"(a1), "r"(a2), "r"(a3), "r"(b0), "r"(b1));
}

// SMEM (uint32 words): sW [0, 32768), sX [32768, 57344)  => 229376 bytes
#define SW_BASE 0
#define SX_BASE 32768
#define SMEM_WORDS 57344

// ---------------------------------------------------------------------------
// Kernel 2: persistent TF32 HMMA GEMM. 384 threads / 12 warps (3 per SMSP).
// M_TILE=96, warp grid 3(M)x4(N), warp tile 32x32. XOR-swizzled smem.
// X tile staged via cp.async (raw fp32 bits -> tf32 RZ truncation), fully
// overlapped with the previous tile's epilogue.
// ---------------------------------------------------------------------------
__global__ __launch_bounds__(THREADS, 1)
void gemm_mma_kernel(const float* __restrict__ vdata,
                     const float* __restrict__ bias,
                     float* __restrict__ out) {
    extern __shared__ uint32_t smem[];
    const uint32_t smem_u32 = (uint32_t)__cvta_generic_to_shared(smem);
    const int tid  = threadIdx.x;
    const int wid  = tid >> 5;
    const int lane = tid & 31;
    const int grp  = lane >> 2;
    const int qp   = lane & 3;
    const int xg   = grp << 2;        // per-thread swizzle XOR

    const int m0 = (wid % 3) * 32;    // warp M band (of 96)
    const int n0 = (wid / 3) * 32;    // warp N quarter (of 128)

    // ---- Stage W^T swizzled image once (8192 uint4) ----
    {
        const uint4* src = reinterpret_cast<const uint4*>(g_wt);
        uint4* dst = reinterpret_cast<uint4*>(smem + SW_BASE);
        #pragma unroll
        for (int i = 0; i < 22; i++) {
            int j = i * THREADS + tid;
            if (j < 8192) dst[j] = src[j];
        }
    }

    float2 bv[4];
    #pragma unroll
    for (int j = 0; j < 4; j++)
        bv[j] = *reinterpret_cast<const float2*>(bias + n0 + j * 8 + qp * 2);

    const float4* A4 = reinterpret_cast<const float4*>(g_x);
    const float4* V4 = reinterpret_cast<const float4*>(vdata);

    // per-thread staging geometry (8 chunks per half)
    int rr[8], cc4[8];
    uint32_t dstA[8], dstV[8];
    #pragma unroll
    for (int i = 0; i < 8; i++) {
        int j = i * THREADS + tid;       // 0..3071
        int r = j >> 5, c4 = j & 31;
        rr[i] = r; cc4[i] = c4;
        int rx = (r & 7) << 2;
        dstA[i] = smem_u32 + (uint32_t)(SX_BASE + r * 256 + ((c4 * 4) ^ rx)) * 4u;
        dstV[i] = smem_u32 + (uint32_t)(SX_BASE + r * 256 + 128 + ((c4 * 4) ^ rx)) * 4u;
    }

    // issue cp.asyncs for a tile's X (raw fp32 bits; OOB rows zero-filled)
    auto issue_tile = [&](int t) {
        int node0 = t * M_TILE;
        #pragma unroll
        for (int i = 0; i < 8; i++) {
            int node = node0 + rr[i];
            unsigned ssz = (node < N_NODES) ? 16u : 0u;
            const float4* sa = A4 + (size_t)node * 32 + cc4[i];
            const float4* sv = V4 + (size_t)node * 32 + cc4[i];
            asm volatile("cp.async.cg.shared.global [%0], [%1], 16, %2;"
                         :: "r"(dstA[i]), "l"(sa), "r"(ssz) : "memory");
            asm volatile("cp.async.cg.shared.global [%0], [%1], 16, %2;"
                         :: "r"(dstV[i]), "l"(sv), "r"(ssz) : "memory");
        }
        asm volatile("cp.async.commit_group;" ::: "memory");
    };

    int t = blockIdx.x;
    if (t < TILES) issue_tile(t);

    while (t < TILES) {
        const int node0 = t * M_TILE;

        asm volatile("cp.async.wait_all;" ::: "memory");
        __syncthreads();

        // re-zero consumed g_x region (safe: cp.async reads completed)
        #pragma unroll
        for (int i = 0; i < 8; i++) {
            int node = node0 + rr[i];
            if (node < N_NODES)
                reinterpret_cast<float4*>(g_x)[(size_t)node * 32 + cc4[i]] =
                    make_float4(0.f, 0.f, 0.f, 0.f);
        }

        // ---- compute: 32 k-steps x (2 m-bands x 4 n-tiles) ----
        float acc[2][4][4];
        #pragma unroll
        for (int mb = 0; mb < 2; mb++)
            #pragma unroll
            for (int j = 0; j < 4; j++)
                #pragma unroll
                for (int c = 0; c < 4; c++) acc[mb][j][c] = 0.f;

        #pragma unroll 4
        for (int ks = 0; ks < 32; ks++) {
            int o  = ((ks * 8) ^ xg) + qp;   // swizzled col offset (k = ks*8+qp)
            int o4 = o ^ 4;                  // k + 4
            uint32_t a[2][4];
            #pragma unroll
            for (int mb = 0; mb < 2; mb++) {
                int base = SX_BASE + (m0 + mb * 16 + grp) * 256;
                a[mb][0] = smem[base + o];
                a[mb][1] = smem[base + 8 * 256 + o];
                a[mb][2] = smem[base + o4];
                a[mb][3] = smem[base + 8 * 256 + o4];
            }
            #pragma unroll
            for (int j = 0; j < 4; j++) {
                int baseB = SW_BASE + (n0 + j * 8 + grp) * 256;
                uint32_t b0 = smem[baseB + o];
                uint32_t b1 = smem[baseB + o4];
                mma_tf32(acc[0][j], a[0][0], a[0][1], a[0][2], a[0][3], b0, b1);
                mma_tf32(acc[1][j], a[1][0], a[1][1], a[1][2], a[1][3], b0, b1);
            }
        }

        __syncthreads();                 // all warps done reading X smem

        int tn = t + GRID_P;
        if (tn < TILES) issue_tile(tn);  // overlap copy with epilogue

        // ---- epilogue (register-only inputs) ----
        #pragma unroll
        for (int mb = 0; mb < 2; mb++) {
            int row_a = node0 + m0 + mb * 16 + grp;
            int row_b = row_a + 8;
            #pragma unroll
            for (int j = 0; j < 4; j++) {
                int col = n0 + j * 8 + qp * 2;
                if (row_a < N_NODES) {
                    float2 o = make_float2(acc[mb][j][0] + bv[j].x,
                                           acc[mb][j][1] + bv[j].y);
                    *reinterpret_cast<float2*>(out + (size_t)row_a * D_OUT + col) = o;
                }
                if (row_b < N_NODES) {
                    float2 o = make_float2(acc[mb][j][2] + bv[j].x,
                                           acc[mb][j][3] + bv[j].y);
                    *reinterpret_cast<float2*>(out + (size_t)row_b * D_OUT + col) = o;
                }
            }
        }
        t = tn;
    }
}

// ---------------------------------------------------------------------------
extern "C" void kernel_launch(void* const* d_in, const int* in_sizes, int n_in,
                              void* d_out, int out_size) {
    const float* vdata   = (const float*)d_in[0];
    const float* edata_a = (const float*)d_in[1];
    const float* edata_b = (const float*)d_in[2];
    const int*   conn_a  = (const int*)d_in[3];
    const int*   conn_b  = (const int*)d_in[4];
    const float* W       = (const float*)d_in[5];
    const float* bias    = (const float*)d_in[6];
    float*       out     = (float*)d_out;

    scatter_prep_kernel<<<SCAT_BLOCKS + 128, 256>>>(
        edata_a, conn_a + N_EDGES, edata_b, conn_b + N_EDGES, W);

    {
        size_t smem_bytes = SMEM_WORDS * sizeof(uint32_t);   // 229376
        cudaFuncSetAttribute(gemm_mma_kernel,
                             cudaFuncAttributeMaxDynamicSharedMemorySize,
                             (int)smem_bytes);
        gemm_mma_kernel<<<GRID_P, THREADS, smem_bytes>>>(vdata, bias, out);
    }
}